// round 2
// baseline (speedup 1.0000x reference)
#include <cuda_runtime.h>
#include <math.h>

#define BB 1024
#define LL 32
#define DD 128
#define NNODE 50000

// scratch: h_s [B, D] between the two kernels
__device__ float g_hs[BB * DD];

__device__ __forceinline__ float sigmoidf_(float x) { return 1.0f / (1.0f + expf(-x)); }

// accumulate acc[l] += S[l][k] * W[k][col] over k=0..127, W row stride = ldw
#define ACCUM_K128(accv, Sbuf, Wptr, ldw, colv)                                   \
    _Pragma("unroll 4") for (int k = 0; k < DD; k++) {                            \
        float w_ = (Wptr)[(k) * (ldw) + (colv)];                                  \
        _Pragma("unroll") for (int l = 0; l < LL; l++)                            \
            accv[l] = fmaf((Sbuf)[l * DD + k], w_, accv[l]);                      \
    }

// ---------------------------------------------------------------------------
// Kernel 1: everything up to h_s.  One CTA per batch element, 128 threads.
// Thread d owns feature column d of every [L, D] intermediate.
// Dynamic smem layout (floats):
//   H[32*128] T1 T2 T3 T4 | sAin[1024] sAout[1024] | sv[128] ssg[128] salpha[32] sred[128]
// ---------------------------------------------------------------------------
__global__ void __launch_bounds__(128) session_kernel(
    const int* __restrict__ items, const float* __restrict__ A_in,
    const float* __restrict__ A_out, const float* __restrict__ inter,
    const int* __restrict__ seq_len, const float* __restrict__ emb,
    const float* __restrict__ W_in, const float* __restrict__ b_in,
    const float* __restrict__ W_out, const float* __restrict__ b_out,
    const float* __restrict__ W_a, const float* __restrict__ U_h,
    const float* __restrict__ b_gru,
    const float* __restrict__ Wi, const float* __restrict__ bi,
    const float* __restrict__ Wh, const float* __restrict__ bh,
    const float* __restrict__ W1, const float* __restrict__ b1,
    const float* __restrict__ W2, const float* __restrict__ b2,
    const float* __restrict__ wq, const float* __restrict__ bq,
    const float* __restrict__ W3, const float* __restrict__ b3)
{
    extern __shared__ float sm[];
    float* H      = sm;
    float* T1     = sm + 4096;
    float* T2     = sm + 8192;
    float* T3     = sm + 12288;
    float* T4     = sm + 16384;
    float* sAin   = sm + 20480;
    float* sAout  = sm + 21504;
    float* sv     = sm + 22528;
    float* ssg    = sm + 22656;
    float* salpha = sm + 22784;
    float* sred   = sm + 22816;  // [l*4 + warp]

    const int b = blockIdx.x;
    const int d = threadIdx.x;          // 0..127 feature dim
    const int warp = d >> 5, lane = d & 31;

    // ---- h = emb_table[items]  -> H
    #pragma unroll 4
    for (int l = 0; l < LL; l++) {
        int idx = items[b * LL + l];
        H[l * DD + d] = emb[idx * DD + d];
    }
    // ---- adjacency tiles
    for (int i = d; i < LL * LL; i += DD) {
        sAin[i]  = A_in[b * LL * LL + i];
        sAout[i] = A_out[b * LL * LL + i];
    }
    __syncthreads();

    float acc[LL];

    // ---- t_in = h @ W_in + b_in  -> T1   (column d, all l)
    {
        float bv = b_in[d];
        #pragma unroll
        for (int l = 0; l < LL; l++) acc[l] = bv;
        ACCUM_K128(acc, H, W_in, DD, d);
        #pragma unroll
        for (int l = 0; l < LL; l++) T1[l * DD + d] = acc[l];
    }
    // ---- t_out = h @ W_out + b_out -> T2
    {
        float bv = b_out[d];
        #pragma unroll
        for (int l = 0; l < LL; l++) acc[l] = bv;
        ACCUM_K128(acc, H, W_out, DD, d);
        #pragma unroll
        for (int l = 0; l < LL; l++) T2[l * DD + d] = acc[l];
    }
    // T1/T2 columns are thread-private; no barrier needed before adjacency.

    // ---- a_in = A_in @ t_in -> T3 ; a_out = A_out @ t_out -> T4
    {
        #pragma unroll
        for (int l = 0; l < LL; l++) acc[l] = 0.0f;
        #pragma unroll 4
        for (int m = 0; m < LL; m++) {
            float tv = T1[m * DD + d];
            #pragma unroll
            for (int l = 0; l < LL; l++) acc[l] = fmaf(sAin[l * LL + m], tv, acc[l]);
        }
        #pragma unroll
        for (int l = 0; l < LL; l++) T3[l * DD + d] = acc[l];
    }
    {
        #pragma unroll
        for (int l = 0; l < LL; l++) acc[l] = 0.0f;
        #pragma unroll 4
        for (int m = 0; m < LL; m++) {
            float tv = T2[m * DD + d];
            #pragma unroll
            for (int l = 0; l < LL; l++) acc[l] = fmaf(sAout[l * LL + m], tv, acc[l]);
        }
        #pragma unroll
        for (int l = 0; l < LL; l++) T4[l * DD + d] = acc[l];
    }
    __syncthreads();  // T3/T4 now read cross-thread

    // ================= GGNN GRU (gi = a@W_a + b_gru, gh = h@U_h) =============
    // r gate -> T1
    {
        float bv = b_gru[d];
        #pragma unroll
        for (int l = 0; l < LL; l++) acc[l] = bv;
        ACCUM_K128(acc, T3, W_a, 3 * DD, d);                 // a_in rows 0..127
        ACCUM_K128(acc, T4, (W_a + DD * 3 * DD), 3 * DD, d); // a_out rows 128..255
        ACCUM_K128(acc, H, U_h, 3 * DD, d);
        #pragma unroll
        for (int l = 0; l < LL; l++) T1[l * DD + d] = sigmoidf_(acc[l]);
    }
    // z gate -> T2
    {
        float bv = b_gru[DD + d];
        #pragma unroll
        for (int l = 0; l < LL; l++) acc[l] = bv;
        ACCUM_K128(acc, T3, W_a, 3 * DD, DD + d);
        ACCUM_K128(acc, T4, (W_a + DD * 3 * DD), 3 * DD, DD + d);
        ACCUM_K128(acc, H, U_h, 3 * DD, DD + d);
        #pragma unroll
        for (int l = 0; l < LL; l++) T2[l * DD + d] = sigmoidf_(acc[l]);
    }
    // n gate + update -> intra (registers)
    {
        float ai[LL], ah[LL];
        float bv = b_gru[2 * DD + d];
        #pragma unroll
        for (int l = 0; l < LL; l++) { ai[l] = bv; ah[l] = 0.0f; }
        ACCUM_K128(ai, T3, W_a, 3 * DD, 2 * DD + d);
        ACCUM_K128(ai, T4, (W_a + DD * 3 * DD), 3 * DD, 2 * DD + d);
        ACCUM_K128(ah, H, U_h, 3 * DD, 2 * DD + d);
        #pragma unroll
        for (int l = 0; l < LL; l++) {
            float r = T1[l * DD + d], z = T2[l * DD + d];
            float n = tanhf(ai[l] + r * ah[l]);
            ai[l] = (1.0f - z) * n + z * H[l * DD + d];  // intra
        }
        __syncthreads();  // all reads of T3/T4/H done before overwrite
        #pragma unroll
        for (int l = 0; l < LL; l++) {
            T3[l * DD + d] = ai[l];                        // intra -> T3
            H[l * DD + d]  = inter[(b * LL + l) * DD + d]; // inter -> H
        }
        __syncthreads();
    }

    // ============ ItemFusing GRUCell (input=intra(T3), hidden=inter(H)) ======
    // r -> T1
    {
        float bv = bi[d] + bh[d];
        #pragma unroll
        for (int l = 0; l < LL; l++) acc[l] = bv;
        ACCUM_K128(acc, T3, Wi, 3 * DD, d);
        ACCUM_K128(acc, H, Wh, 3 * DD, d);
        #pragma unroll
        for (int l = 0; l < LL; l++) T1[l * DD + d] = sigmoidf_(acc[l]);
    }
    // z -> T2
    {
        float bv = bi[DD + d] + bh[DD + d];
        #pragma unroll
        for (int l = 0; l < LL; l++) acc[l] = bv;
        ACCUM_K128(acc, T3, Wi, 3 * DD, DD + d);
        ACCUM_K128(acc, H, Wh, 3 * DD, DD + d);
        #pragma unroll
        for (int l = 0; l < LL; l++) T2[l * DD + d] = sigmoidf_(acc[l]);
    }
    // n + update -> final -> T4
    {
        float ai[LL], ah[LL];
        float bvi = bi[2 * DD + d], bvh = bh[2 * DD + d];
        #pragma unroll
        for (int l = 0; l < LL; l++) { ai[l] = bvi; ah[l] = bvh; }
        ACCUM_K128(ai, T3, Wi, 3 * DD, 2 * DD + d);
        ACCUM_K128(ah, H, Wh, 3 * DD, 2 * DD + d);
        #pragma unroll
        for (int l = 0; l < LL; l++) {
            float r = T1[l * DD + d], z = T2[l * DD + d];
            float n = tanhf(ai[l] + r * ah[l]);
            T4[l * DD + d] = (1.0f - z) * n + z * H[l * DD + d];  // final
        }
    }

    // =========================== attention readout ===========================
    const int slen = seq_len[b];
    sv[d] = T4[(slen - 1) * DD + d];  // column d is thread-private
    __syncthreads();                   // publish T4 + sv

    // q1[d] = (v_n @ W1 + b1)[d]
    float q1 = b1[d];
    #pragma unroll 4
    for (int k = 0; k < DD; k++) q1 = fmaf(sv[k], W1[k * DD + d], q1);

    // acc[l] = (final @ W2 + b2)[l][d]
    {
        float bv = b2[d];
        #pragma unroll
        for (int l = 0; l < LL; l++) acc[l] = bv;
        ACCUM_K128(acc, T4, W2, DD, d);
    }
    // alpha[l] = sum_d sigmoid(q1+acc)*wq[d] + bq
    {
        float wqd = wq[d];
        #pragma unroll
        for (int l = 0; l < LL; l++) {
            float g = sigmoidf_(q1 + acc[l]) * wqd;
            #pragma unroll
            for (int off = 16; off > 0; off >>= 1)
                g += __shfl_xor_sync(0xffffffffu, g, off);
            if (lane == 0) sred[l * 4 + warp] = g;
        }
        __syncthreads();
        if (d < LL) {
            float a_ = sred[d * 4] + sred[d * 4 + 1] + sred[d * 4 + 2] + sred[d * 4 + 3] + bq[0];
            salpha[d] = (d < slen) ? a_ : 0.0f;  // fold mask into alpha
        }
        __syncthreads();
    }
    // s_g[d] = sum_l alpha[l]*final[l][d]
    {
        float sg = 0.0f;
        #pragma unroll
        for (int l = 0; l < LL; l++) sg = fmaf(salpha[l], T4[l * DD + d], sg);
        ssg[d] = sg;
    }
    __syncthreads();
    // h_s = concat(v_n, s_g) @ W3 + b3
    {
        float hs = b3[d];
        #pragma unroll 4
        for (int k = 0; k < DD; k++) hs = fmaf(sv[k], W3[k * DD + d], hs);
        #pragma unroll 4
        for (int k = 0; k < DD; k++) hs = fmaf(ssg[k], W3[(DD + k) * DD + d], hs);
        g_hs[b * DD + d] = hs;
    }
}

// ---------------------------------------------------------------------------
// Kernel 2: scores[b, n] = dot(h_s[b], emb[n]).  64x64 tile, K=128 resident.
// smem rows padded to 132 floats (stride%32 = 4 -> <=2-way LDS.128 conflicts).
// ---------------------------------------------------------------------------
#define TM 64
#define TN 64
#define PAD 132

__global__ void __launch_bounds__(256) scores_kernel(const float* __restrict__ emb,
                                                     float* __restrict__ out)
{
    extern __shared__ float sm[];
    float* hsS  = sm;              // [64][132]
    float* embS = sm + TM * PAD;   // [64][132]

    const int n0 = blockIdx.x * TN;
    const int b0 = blockIdx.y * TM;
    const int tid = threadIdx.x;

    // load h_s tile: 64 rows x 128 k (32 float4/row), 8 float4 per thread
    for (int i = tid; i < TM * 32; i += 256) {
        int row = i >> 5, c = (i & 31) << 2;
        float4 v = *(const float4*)&g_hs[(b0 + row) * DD + c];
        *(float4*)&hsS[row * PAD + c] = v;
    }
    // load emb tile (guard n >= NNODE with zeros)
    for (int i = tid; i < TN * 32; i += 256) {
        int row = i >> 5, c = (i & 31) << 2;
        int n = n0 + row;
        float4 v = make_float4(0.f, 0.f, 0.f, 0.f);
        if (n < NNODE) v = *(const float4*)&emb[n * DD + c];
        *(float4*)&embS[row * PAD + c] = v;
    }
    __syncthreads();

    const int tn = tid & 15, tm = tid >> 4;  // 16 x 16 thread grid, 4x4 micro
    float accm[4][4] = {};

    #pragma unroll 8
    for (int k = 0; k < DD; k += 4) {
        float4 av[4], bv[4];
        #pragma unroll
        for (int i = 0; i < 4; i++) av[i] = *(const float4*)&hsS[(tm * 4 + i) * PAD + k];
        #pragma unroll
        for (int j = 0; j < 4; j++) bv[j] = *(const float4*)&embS[(tn * 4 + j) * PAD + k];
        #pragma unroll
        for (int i = 0; i < 4; i++)
            #pragma unroll
            for (int j = 0; j < 4; j++) {
                accm[i][j] = fmaf(av[i].x, bv[j].x, accm[i][j]);
                accm[i][j] = fmaf(av[i].y, bv[j].y, accm[i][j]);
                accm[i][j] = fmaf(av[i].z, bv[j].z, accm[i][j]);
                accm[i][j] = fmaf(av[i].w, bv[j].w, accm[i][j]);
            }
    }

    #pragma unroll
    for (int i = 0; i < 4; i++) {
        int bb = b0 + tm * 4 + i;
        int n = n0 + tn * 4;
        if (n + 3 < NNODE) {
            *(float4*)&out[bb * NNODE + n] =
                make_float4(accm[i][0], accm[i][1], accm[i][2], accm[i][3]);
        } else {
            #pragma unroll
            for (int j = 0; j < 4; j++)
                if (n + j < NNODE) out[bb * NNODE + n + j] = accm[i][j];
        }
    }
}

// ---------------------------------------------------------------------------
extern "C" void kernel_launch(void* const* d_in, const int* in_sizes, int n_in,
                              void* d_out, int out_size)
{
    (void)in_sizes; (void)n_in; (void)out_size;
    const int*   items   = (const int*)d_in[0];
    const float* A_in    = (const float*)d_in[1];
    const float* A_out   = (const float*)d_in[2];
    const float* inter   = (const float*)d_in[3];
    const int*   seq_len = (const int*)d_in[4];
    const float* emb     = (const float*)d_in[5];
    const float* W_in    = (const float*)d_in[6];
    const float* b_in    = (const float*)d_in[7];
    const float* W_out   = (const float*)d_in[8];
    const float* b_out   = (const float*)d_in[9];
    const float* W_a     = (const float*)d_in[10];
    const float* U_h     = (const float*)d_in[11];
    const float* b_gru   = (const float*)d_in[12];
    const float* Wi      = (const float*)d_in[13];
    const float* bi      = (const float*)d_in[14];
    const float* Wh      = (const float*)d_in[15];
    const float* bh      = (const float*)d_in[16];
    const float* W1      = (const float*)d_in[17];
    const float* b1      = (const float*)d_in[18];
    const float* W2      = (const float*)d_in[19];
    const float* b2      = (const float*)d_in[20];
    const float* wq      = (const float*)d_in[21];
    const float* bq      = (const float*)d_in[22];
    const float* W3      = (const float*)d_in[23];
    const float* b3      = (const float*)d_in[24];
    float* out = (float*)d_out;

    const int smem_session = 22944 * 4;             // 91,776 B
    const int smem_scores  = 2 * TM * PAD * 4;      // 67,584 B
    cudaFuncSetAttribute(session_kernel, cudaFuncAttributeMaxDynamicSharedMemorySize,
                         smem_session);
    cudaFuncSetAttribute(scores_kernel, cudaFuncAttributeMaxDynamicSharedMemorySize,
                         smem_scores);

    session_kernel<<<BB, 128, smem_session>>>(
        items, A_in, A_out, inter, seq_len, emb,
        W_in, b_in, W_out, b_out, W_a, U_h, b_gru,
        Wi, bi, Wh, bh, W1, b1, W2, b2, wq, bq, W3, b3);

    dim3 grid((NNODE + TN - 1) / TN, BB / TM);
    scores_kernel<<<grid, 256, smem_scores>>>(emb, out);
}

// round 3
// speedup vs baseline: 1.7590x; 1.7590x over previous
#include <cuda_runtime.h>
#include <math.h>

#define BB 1024
#define LL 32
#define DD 128
#define NNODE 50000

typedef unsigned long long ull;

// scratch: h_s [B, D] between the two kernels
__device__ float g_hs[BB * DD];

__device__ __forceinline__ float sigmoidf_(float x) { return 1.0f / (1.0f + expf(-x)); }

// ---- packed fp32x2 helpers (sm_100+: fma.rn.f32x2) ------------------------
__device__ __forceinline__ void fma2(ull& d, ull a, ull b) {
    asm("fma.rn.f32x2 %0, %1, %2, %0;" : "+l"(d) : "l"(a), "l"(b));
}
__device__ __forceinline__ ull pk2(float lo, float hi) {
    ull r; asm("mov.b64 %0, {%1, %2};" : "=l"(r) : "f"(lo), "f"(hi)); return r;
}
__device__ __forceinline__ float psum(ull a) {
    float lo, hi; asm("mov.b64 {%0, %1}, %2;" : "=f"(lo), "=f"(hi) : "l"(a));
    return lo + hi;
}

// acc{r,z,n}[l] += sum_k S[(l0+l)][k] * W[k][c{0,1,2}]   (16 l's, packed k-pairs)
__device__ __forceinline__ void acc3(ull* ar, ull* az, ull* an,
                                     const float* S,
                                     const float* __restrict__ W, int ldw,
                                     int c0, int c1, int c2, int l0)
{
    #pragma unroll 2
    for (int k = 0; k < DD; k += 4) {
        const float* wb = W + (size_t)k * ldw;
        ull w00 = pk2(wb[c0],         wb[ldw + c0]);
        ull w01 = pk2(wb[2*ldw + c0], wb[3*ldw + c0]);
        ull w10 = pk2(wb[c1],         wb[ldw + c1]);
        ull w11 = pk2(wb[2*ldw + c1], wb[3*ldw + c1]);
        ull w20 = pk2(wb[c2],         wb[ldw + c2]);
        ull w21 = pk2(wb[2*ldw + c2], wb[3*ldw + c2]);
        #pragma unroll
        for (int l = 0; l < 16; l++) {
            ulonglong2 s = *(const ulonglong2*)&S[(l0 + l) * DD + k];
            fma2(ar[l], s.x, w00); fma2(ar[l], s.y, w01);
            fma2(az[l], s.x, w10); fma2(az[l], s.y, w11);
            fma2(an[l], s.x, w20); fma2(an[l], s.y, w21);
        }
    }
}

// a0[l] += S@W0[:,c], a1[l] += S@W1[:,c]   (16 l's, ldw = DD)
__device__ __forceinline__ void acc2w(ull* a0, ull* a1, const float* S,
                                      const float* __restrict__ W0,
                                      const float* __restrict__ W1, int c, int l0)
{
    #pragma unroll 2
    for (int k = 0; k < DD; k += 4) {
        ull w00 = pk2(W0[k*DD + c],     W0[(k+1)*DD + c]);
        ull w01 = pk2(W0[(k+2)*DD + c], W0[(k+3)*DD + c]);
        ull w10 = pk2(W1[k*DD + c],     W1[(k+1)*DD + c]);
        ull w11 = pk2(W1[(k+2)*DD + c], W1[(k+3)*DD + c]);
        #pragma unroll
        for (int l = 0; l < 16; l++) {
            ulonglong2 s = *(const ulonglong2*)&S[(l0 + l) * DD + k];
            fma2(a0[l], s.x, w00); fma2(a0[l], s.y, w01);
            fma2(a1[l], s.x, w10); fma2(a1[l], s.y, w11);
        }
    }
}

// a0[l] += S@W[:,c]   (32 l's)
__device__ __forceinline__ void acc1(ull* a0, const float* S,
                                     const float* __restrict__ W, int ldw, int c)
{
    #pragma unroll 2
    for (int k = 0; k < DD; k += 4) {
        ull w0 = pk2(W[k*ldw + c],     W[(k+1)*ldw + c]);
        ull w1 = pk2(W[(k+2)*ldw + c], W[(k+3)*ldw + c]);
        #pragma unroll
        for (int l = 0; l < LL; l++) {
            ulonglong2 s = *(const ulonglong2*)&S[l * DD + k];
            fma2(a0[l], s.x, w0); fma2(a0[l], s.y, w1);
        }
    }
}

// ---------------------------------------------------------------------------
// Kernel 1: everything up to h_s.  One CTA per batch element, 128 threads.
// Thread d owns feature column d of every [L, D] intermediate.
// ---------------------------------------------------------------------------
__global__ void __launch_bounds__(128) session_kernel(
    const int* __restrict__ items, const float* __restrict__ A_in,
    const float* __restrict__ A_out, const float* __restrict__ inter,
    const int* __restrict__ seq_len, const float* __restrict__ emb,
    const float* __restrict__ W_in, const float* __restrict__ b_in,
    const float* __restrict__ W_out, const float* __restrict__ b_out,
    const float* __restrict__ W_a, const float* __restrict__ U_h,
    const float* __restrict__ b_gru,
    const float* __restrict__ Wi, const float* __restrict__ bi,
    const float* __restrict__ Wh, const float* __restrict__ bh,
    const float* __restrict__ W1, const float* __restrict__ b1,
    const float* __restrict__ W2, const float* __restrict__ b2,
    const float* __restrict__ wq, const float* __restrict__ bq,
    const float* __restrict__ W3, const float* __restrict__ b3)
{
    extern __shared__ float sm[];
    float* H      = sm;
    float* T1     = sm + 4096;
    float* T2     = sm + 8192;
    float* T3     = sm + 12288;
    float* T4     = sm + 16384;
    float* sAin   = sm + 20480;
    float* sAout  = sm + 21504;
    float* sv     = sm + 22528;
    float* ssg    = sm + 22656;
    float* salpha = sm + 22784;
    float* sred   = sm + 22816;

    const int b = blockIdx.x;
    const int d = threadIdx.x;
    const int warp = d >> 5, lane = d & 31;

    // ---- h = emb_table[items] -> H ; adjacency tiles
    #pragma unroll 4
    for (int l = 0; l < LL; l++) {
        int idx = items[b * LL + l];
        H[l * DD + d] = emb[idx * DD + d];
    }
    for (int i = d; i < LL * LL; i += DD) {
        sAin[i]  = A_in[b * LL * LL + i];
        sAout[i] = A_out[b * LL * LL + i];
    }
    __syncthreads();

    // ---- t_in = h@W_in + b_in -> T1 ; t_out = h@W_out + b_out -> T2
    for (int h = 0; h < 2; h++) {
        const int l0 = h * 16;
        ull a0[16], a1[16];
        #pragma unroll
        for (int l = 0; l < 16; l++) { a0[l] = 0ull; a1[l] = 0ull; }
        acc2w(a0, a1, H, W_in, W_out, d, l0);
        float bv0 = b_in[d], bv1 = b_out[d];
        #pragma unroll
        for (int l = 0; l < 16; l++) {
            T1[(l0 + l) * DD + d] = psum(a0[l]) + bv0;
            T2[(l0 + l) * DD + d] = psum(a1[l]) + bv1;
        }
    }
    // T1/T2 columns are thread-private; no barrier needed before adjacency.

    // ---- a_in = A_in @ t_in -> T3 ; a_out = A_out @ t_out -> T4 (scalar, tiny)
    {
        float acc[LL];
        #pragma unroll
        for (int l = 0; l < LL; l++) acc[l] = 0.0f;
        #pragma unroll 4
        for (int m = 0; m < LL; m++) {
            float tv = T1[m * DD + d];
            #pragma unroll
            for (int l = 0; l < LL; l++) acc[l] = fmaf(sAin[l * LL + m], tv, acc[l]);
        }
        #pragma unroll
        for (int l = 0; l < LL; l++) T3[l * DD + d] = acc[l];

        #pragma unroll
        for (int l = 0; l < LL; l++) acc[l] = 0.0f;
        #pragma unroll 4
        for (int m = 0; m < LL; m++) {
            float tv = T2[m * DD + d];
            #pragma unroll
            for (int l = 0; l < LL; l++) acc[l] = fmaf(sAout[l * LL + m], tv, acc[l]);
        }
        #pragma unroll
        for (int l = 0; l < LL; l++) T4[l * DD + d] = acc[l];
    }
    __syncthreads();  // publish T3/T4

    // ================= GGNN GRU ==============================================
    // intra -> T1 (reusing dead t_in slots; column-private)
    for (int h = 0; h < 2; h++) {
        const int l0 = h * 16;
        ull ar[16], az[16], an[16];
        #pragma unroll
        for (int l = 0; l < 16; l++) { ar[l] = az[l] = an[l] = 0ull; }
        acc3(ar, az, an, T3, W_a,              3*DD, d, DD + d, 2*DD + d, l0);
        acc3(ar, az, an, T4, W_a + DD * 3*DD,  3*DD, d, DD + d, 2*DD + d, l0);
        float inv[16];
        {
            float br = b_gru[d], bz = b_gru[DD + d], bn = b_gru[2*DD + d];
            #pragma unroll
            for (int l = 0; l < 16; l++) {
                T1[(l0 + l) * DD + d] = psum(ar[l]) + br;   // i_r spill
                T2[(l0 + l) * DD + d] = psum(az[l]) + bz;   // i_z spill
                inv[l] = psum(an[l]) + bn;                  // i_n in regs
            }
        }
        #pragma unroll
        for (int l = 0; l < 16; l++) { ar[l] = az[l] = an[l] = 0ull; }
        acc3(ar, az, an, H, U_h, 3*DD, d, DD + d, 2*DD + d, l0);
        #pragma unroll
        for (int l = 0; l < 16; l++) {
            float r = sigmoidf_(T1[(l0 + l) * DD + d] + psum(ar[l]));
            float z = sigmoidf_(T2[(l0 + l) * DD + d] + psum(az[l]));
            float n = tanhf(inv[l] + r * psum(an[l]));
            T1[(l0 + l) * DD + d] = (1.0f - z) * n + z * H[(l0 + l) * DD + d]; // intra
        }
    }
    __syncthreads();  // all cross-thread reads of T3/T4/H done
    #pragma unroll 4
    for (int l = 0; l < LL; l++) {
        T3[l * DD + d] = T1[l * DD + d];               // intra -> T3
        H[l * DD + d]  = inter[(b * LL + l) * DD + d]; // inter -> H
    }
    __syncthreads();

    // ============ ItemFusing GRUCell (input=intra(T3), hidden=inter(H)) ======
    for (int h = 0; h < 2; h++) {
        const int l0 = h * 16;
        ull ar[16], az[16], an[16];
        #pragma unroll
        for (int l = 0; l < 16; l++) { ar[l] = az[l] = an[l] = 0ull; }
        acc3(ar, az, an, T3, Wi, 3*DD, d, DD + d, 2*DD + d, l0);
        float inv[16];
        {
            float br = bi[d], bz = bi[DD + d], bn = bi[2*DD + d];
            #pragma unroll
            for (int l = 0; l < 16; l++) {
                T1[(l0 + l) * DD + d] = psum(ar[l]) + br;
                T2[(l0 + l) * DD + d] = psum(az[l]) + bz;
                inv[l] = psum(an[l]) + bn;
            }
        }
        #pragma unroll
        for (int l = 0; l < 16; l++) { ar[l] = az[l] = an[l] = 0ull; }
        acc3(ar, az, an, H, Wh, 3*DD, d, DD + d, 2*DD + d, l0);
        {
            float br = bh[d], bz = bh[DD + d], bn = bh[2*DD + d];
            #pragma unroll
            for (int l = 0; l < 16; l++) {
                float r = sigmoidf_(T1[(l0 + l) * DD + d] + psum(ar[l]) + br);
                float z = sigmoidf_(T2[(l0 + l) * DD + d] + psum(az[l]) + bz);
                float n = tanhf(inv[l] + r * (psum(an[l]) + bn));
                T4[(l0 + l) * DD + d] = (1.0f - z) * n + z * H[(l0 + l) * DD + d];
            }
        }
    }

    // =========================== attention readout ===========================
    const int slen = seq_len[b];
    sv[d] = T4[(slen - 1) * DD + d];  // own column of T4
    __syncthreads();                   // publish T4 + sv

    float q1 = b1[d];
    #pragma unroll 4
    for (int k = 0; k < DD; k++) q1 = fmaf(sv[k], W1[k * DD + d], q1);

    float acc[LL];
    {
        ull aw[LL];
        #pragma unroll
        for (int l = 0; l < LL; l++) aw[l] = 0ull;
        acc1(aw, T4, W2, DD, d);
        float bv = b2[d];
        #pragma unroll
        for (int l = 0; l < LL; l++) acc[l] = psum(aw[l]) + bv;
    }
    {
        float wqd = wq[d];
        #pragma unroll
        for (int l = 0; l < LL; l++) {
            float g = sigmoidf_(q1 + acc[l]) * wqd;
            #pragma unroll
            for (int off = 16; off > 0; off >>= 1)
                g += __shfl_xor_sync(0xffffffffu, g, off);
            if (lane == 0) sred[l * 4 + warp] = g;
        }
        __syncthreads();
        if (d < LL) {
            float a_ = sred[d * 4] + sred[d * 4 + 1] + sred[d * 4 + 2] + sred[d * 4 + 3] + bq[0];
            salpha[d] = (d < slen) ? a_ : 0.0f;
        }
        __syncthreads();
    }
    {
        float sg = 0.0f;
        #pragma unroll
        for (int l = 0; l < LL; l++) sg = fmaf(salpha[l], T4[l * DD + d], sg);
        ssg[d] = sg;
    }
    __syncthreads();
    {
        float hs = b3[d];
        #pragma unroll 4
        for (int k = 0; k < DD; k++) hs = fmaf(sv[k], W3[k * DD + d], hs);
        #pragma unroll 4
        for (int k = 0; k < DD; k++) hs = fmaf(ssg[k], W3[(DD + k) * DD + d], hs);
        g_hs[b * DD + d] = hs;
    }
}

// ---------------------------------------------------------------------------
// Kernel 2: scores = h_s @ emb^T.  128x128 block, K=128 resident, 8x8/thread,
// packed f32x2 over k-pairs.  16B-chunk XOR swizzle: chunk c4 of row r stored
// at c4 ^ ((r>>3)&7)  -> b-loads at fixed k hit distinct bank groups.
// ---------------------------------------------------------------------------
#define SBM 128
#define SBN 128

__global__ void __launch_bounds__(256) scores_kernel(const float* __restrict__ emb,
                                                     float* __restrict__ out)
{
    extern __shared__ float sm[];
    float* aS = sm;                 // [128][128] swizzled
    float* bS = sm + SBM * DD;      // [128][128] swizzled

    const int n0 = blockIdx.x * SBN;
    const int b0 = blockIdx.y * SBM;
    const int tid = threadIdx.x;

    for (int i = tid; i < 128 * 32; i += 256) {
        int r = i >> 5, c4 = i & 31;
        int xp = (c4 ^ ((r >> 3) & 7)) << 2;
        *(float4*)&aS[r * DD + xp] = *(const float4*)&g_hs[(b0 + r) * DD + (c4 << 2)];
        int n = n0 + r;
        float4 v = make_float4(0.f, 0.f, 0.f, 0.f);
        if (n < NNODE) v = *(const float4*)&emb[n * DD + (c4 << 2)];
        *(float4*)&bS[r * DD + xp] = v;
    }
    __syncthreads();

    const int tm = tid >> 4, tn = tid & 15;
    const float* ap = aS + tm * 8 * DD;
    const float* bp = bS + tn * 8 * DD;
    const int xm = tm & 7, xn = tn & 7;

    ull acc[8][8];
    #pragma unroll
    for (int i = 0; i < 8; i++)
        #pragma unroll
        for (int j = 0; j < 8; j++) acc[i][j] = 0ull;

    #pragma unroll 4
    for (int q = 0; q < 32; q++) {
        const int ka = (q ^ xm) << 2;
        const int kb = (q ^ xn) << 2;
        ulonglong2 av[8], bv[8];
        #pragma unroll
        for (int i = 0; i < 8; i++) av[i] = *(const ulonglong2*)&ap[i * DD + ka];
        #pragma unroll
        for (int j = 0; j < 8; j++) bv[j] = *(const ulonglong2*)&bp[j * DD + kb];
        #pragma unroll
        for (int i = 0; i < 8; i++)
            #pragma unroll
            for (int j = 0; j < 8; j++) {
                fma2(acc[i][j], av[i].x, bv[j].x);
                fma2(acc[i][j], av[i].y, bv[j].y);
            }
    }

    const int nb = n0 + tn * 8;
    const bool full = (n0 + SBN <= NNODE);
    #pragma unroll
    for (int i = 0; i < 8; i++) {
        int row = b0 + tm * 8 + i;
        float* op = out + (size_t)row * NNODE + nb;
        float v[8];
        #pragma unroll
        for (int j = 0; j < 8; j++) v[j] = psum(acc[i][j]);
        if (full) {
            *(float4*)op       = make_float4(v[0], v[1], v[2], v[3]);
            *(float4*)(op + 4) = make_float4(v[4], v[5], v[6], v[7]);
        } else {
            #pragma unroll
            for (int j = 0; j < 8; j++)
                if (nb + j < NNODE) op[j] = v[j];
        }
    }
}

// ---------------------------------------------------------------------------
extern "C" void kernel_launch(void* const* d_in, const int* in_sizes, int n_in,
                              void* d_out, int out_size)
{
    (void)in_sizes; (void)n_in; (void)out_size;
    const int*   items   = (const int*)d_in[0];
    const float* A_in    = (const float*)d_in[1];
    const float* A_out   = (const float*)d_in[2];
    const float* inter   = (const float*)d_in[3];
    const int*   seq_len = (const int*)d_in[4];
    const float* emb     = (const float*)d_in[5];
    const float* W_in    = (const float*)d_in[6];
    const float* b_in    = (const float*)d_in[7];
    const float* W_out   = (const float*)d_in[8];
    const float* b_out   = (const float*)d_in[9];
    const float* W_a     = (const float*)d_in[10];
    const float* U_h     = (const float*)d_in[11];
    const float* b_gru   = (const float*)d_in[12];
    const float* Wi      = (const float*)d_in[13];
    const float* bi      = (const float*)d_in[14];
    const float* Wh      = (const float*)d_in[15];
    const float* bh      = (const float*)d_in[16];
    const float* W1      = (const float*)d_in[17];
    const float* b1      = (const float*)d_in[18];
    const float* W2      = (const float*)d_in[19];
    const float* b2      = (const float*)d_in[20];
    const float* wq      = (const float*)d_in[21];
    const float* bq      = (const float*)d_in[22];
    const float* W3      = (const float*)d_in[23];
    const float* b3      = (const float*)d_in[24];
    float* out = (float*)d_out;

    const int smem_session = 22944 * 4;              // 91,776 B
    const int smem_scores  = 2 * SBM * DD * 4;       // 131,072 B
    cudaFuncSetAttribute(session_kernel, cudaFuncAttributeMaxDynamicSharedMemorySize,
                         smem_session);
    cudaFuncSetAttribute(scores_kernel, cudaFuncAttributeMaxDynamicSharedMemorySize,
                         smem_scores);

    session_kernel<<<BB, 128, smem_session>>>(
        items, A_in, A_out, inter, seq_len, emb,
        W_in, b_in, W_out, b_out, W_a, U_h, b_gru,
        Wi, bi, Wh, bh, W1, b1, W2, b2, wq, bq, W3, b3);

    dim3 grid((NNODE + SBN - 1) / SBN, BB / SBM);
    scores_kernel<<<grid, 256, smem_scores>>>(emb, out);
}